// round 12
// baseline (speedup 1.0000x reference)
#include <cuda_runtime.h>

// Not-a-knot cubic spline upsample, 512 x 8192 fp32 -> 512 x 32768 fp32.
// [1,4,1] tridiagonal inverse = exponential Green's function (lam = sqrt(3)-2)
// composed with the 6*[1,-2,1] rhs into a 17-tap FIR on y -> M is LOCAL.
//
// FIR phase builds a per-interval cubic-coefficient float4 table (each interval
// built ONCE). step = 8191/32767: point m of chunk cg lies in interval cg-1
// iff 8191*m < 3*cg (exact integer predicate) -> static warp-uniform A/B
// patterns; eval per chunk = 2 conflict-free LDS.128 + (MUL+SUB+3FMA)/point,
// stride-NTHR chunk mapping keeps STG.128 fully coalesced.

#define W_DIM  8192
#define NTHR   256
#define TILE_I 1024
#define KT     8
#define SYN    1056
#define SCN    1026      // interval slots: slot s = interval kbase-1+s

#define LAM   (-0.26794919243112270647f)   // sqrt(3) - 2
#define ACOEF (0.28867513459481288225f)    // 1 / (2*sqrt(3))

__device__ __forceinline__ float4 make_coef(float y0, float y1, float m0, float m1) {
    float4 c;
    c.x = y0;
    c.y = fmaf(fmaf(2.f, m0, m1), -(1.f / 6.f), y1 - y0);
    c.z = 0.5f * m0;
    c.w = (m1 - m0) * (1.f / 6.f);
    return c;
}

__global__ __launch_bounds__(NTHR, 6)
void spline_kernel(const float* __restrict__ x, float* __restrict__ out,
                   int nout, float step) {
    __shared__ __align__(16) float  sy[SYN];
    __shared__ __align__(16) float4 sC[SCN];

    const int tid = threadIdx.x;
    const int n = W_DIM - 4;
    const int row = blockIdx.y;
    const int kbase = blockIdx.x * TILE_I;

    const float* xr = x + (size_t)row * W_DIM;
    float* outr = out + (size_t)row * nout + kbase * 4;

    const int ilo = (kbase >= 16) ? (kbase - 16) : 0;
    int ihi = kbase + TILE_I + 16; if (ihi > W_DIM) ihi = W_DIM;
    const int NY = ihi - ilo;

    // ---- load y slice (+halo), aligned float4 ----
    {
        const float4* x4 = (const float4*)(xr + ilo);
        float4* sy4 = (float4*)sy;
        for (int v = tid; v < (NY >> 2); v += NTHR) sy4[v] = x4[v];
    }
    __syncthreads();

    // ---- FIR (17-tap) for M, fused per-interval coefficient build ----
    {
        const float C0 = -4.3923048f;
        const float C[KT] = { 2.7846097f, -0.7461340f, 0.1999261f, -0.0535701f,
                              0.0143541f, -0.0038462f, 0.0010306f, -0.0002761f };
        int gfirst = kbase - 1; if (gfirst < 20) gfirst = 20;
        int glast = kbase + TILE_I - 1;                 // interval kbase+1023
        if (glast > W_DIM - 22) glast = W_DIM - 22;
        const int lstart = ((gfirst - ilo) >> 2) << 2;  // >= 8, 4-aligned
        const int nch = ((glast - ilo - lstart) >> 2) + 1;
        for (int c = tid; c < nch; c += NTHR) {
            const int li0 = lstart + 4 * c;
            float win[24];                              // y[li0-8 .. li0+15]
            const float4* ws = (const float4*)(sy + li0 - 8);
            #pragma unroll
            for (int v = 0; v < 6; ++v) ((float4*)win)[v] = ws[v];
            float M5[5];
            #pragma unroll
            for (int m = 0; m < 5; ++m) {
                float acc = C0 * win[8 + m];
                #pragma unroll
                for (int k = 1; k <= KT; ++k)
                    acc = fmaf(C[k - 1], win[8 + m - k] + win[8 + m + k], acc);
                M5[m] = acc;
            }
            const int gi0 = ilo + li0;
            #pragma unroll
            for (int m = 0; m < 4; ++m) {
                const int gi = gi0 + m;
                if (gi >= gfirst && gi <= glast)
                    sC[gi - kbase + 1] =
                        make_coef(win[8 + m], win[9 + m], M5[m], M5[m + 1]);
            }
        }
    }

    // ---- left edge (row-start tile): intervals 0..19 exact via Green sums ----
    if (kbase == 0 && tid < 20) {
        const float M1 = sy[2] - 2.f * sy[1] + sy[0];
        float SL = 0.f, lp = LAM;
        #pragma unroll 4
        for (int j = 0; j < 24; ++j) {
            float b = 6.f * (sy[j + 3] - 2.f * sy[j + 2] + sy[j + 1]);
            if (j == 0) b -= M1;
            SL = fmaf(lp, b, SL);
            lp *= LAM;
        }
        float Mv[2];
        #pragma unroll 1
        for (int u = 0; u < 2; ++u) {
            const int idx = tid + u;                    // knot 0..20
            if (idx == 1) { Mv[u] = M1; continue; }
            const int jj = (idx == 0) ? 0 : idx - 2;
            float acc = 0.f, p = 1.f;
            #pragma unroll 1
            for (int d = 0; d <= 12; ++d) {
                const int j = jj - d;
                if (j >= 0) {
                    float b = 6.f * (sy[j + 3] - 2.f * sy[j + 2] + sy[j + 1]);
                    if (j == 0) b -= M1;
                    acc = fmaf(p, b, acc);
                }
                p *= LAM;
            }
            p = LAM;
            #pragma unroll 1
            for (int d = 1; d <= 12; ++d) {
                const int j = jj + d;                   // always < n
                float b = 6.f * (sy[j + 3] - 2.f * sy[j + 2] + sy[j + 1]);
                acc = fmaf(p, b, acc);
                p *= LAM;
            }
            float pw = LAM;                             // lam^{jj+1}
            for (int s = 0; s < jj; ++s) pw *= LAM;
            acc -= pw * SL;
            float v = ACOEF * acc;
            Mv[u] = (idx == 0) ? (2.f * M1 - v) : v;
        }
        const float4 cf = make_coef(sy[tid], sy[tid + 1], Mv[0], Mv[1]);
        sC[tid + 1] = cf;                               // interval tid
        if (tid == 0) sC[0] = cf;                       // pseudo interval -1
    }

    // ---- right edge (row-end tile): intervals W-21..W-2 exact ----
    if (kbase + TILE_I == W_DIM && tid >= 32 && tid < 52) {
        const int t = tid - 32;                         // 0..19
        const int gi = (W_DIM - 21) + t;                // interval 8171..8190
        const int lW = W_DIM - ilo;
        const float Mn2 = sy[lW - 1] - 2.f * sy[lW - 2] + sy[lW - 3];
        float SR = 0.f, lp = LAM;
        #pragma unroll 4
        for (int m = 0; m < 24; ++m) {
            const int j = n - 1 - m;
            float b = 6.f * (sy[j + 3 - ilo] - 2.f * sy[j + 2 - ilo] + sy[j + 1 - ilo]);
            if (j == n - 1) b -= Mn2;
            SR = fmaf(lp, b, SR);
            lp *= LAM;
        }
        float Mv[2];
        #pragma unroll 1
        for (int u = 0; u < 2; ++u) {
            const int idx = gi + u;                     // knot 8171..8191
            if (idx == W_DIM - 2) { Mv[u] = Mn2; continue; }
            const int jj = (idx == W_DIM - 1) ? (n - 1) : (idx - 2);
            float acc = 0.f, p = 1.f;
            #pragma unroll 1
            for (int d = 0; d <= 12; ++d) {
                const int j = jj - d;                   // always >= 0
                float b = 6.f * (sy[j + 3 - ilo] - 2.f * sy[j + 2 - ilo] + sy[j + 1 - ilo]);
                if (j == n - 1) b -= Mn2;
                acc = fmaf(p, b, acc);
                p *= LAM;
            }
            p = LAM;
            #pragma unroll 1
            for (int d = 1; d <= 12; ++d) {
                const int j = jj + d;
                if (j < n) {
                    float b = 6.f * (sy[j + 3 - ilo] - 2.f * sy[j + 2 - ilo] + sy[j + 1 - ilo]);
                    acc = fmaf(p, b, acc);
                }
                p *= LAM;
            }
            float pw = LAM;                             // lam^{n-jj}
            for (int s = 0; s < n - 1 - jj; ++s) pw *= LAM;
            acc -= pw * SR;
            float v = ACOEF * acc;
            Mv[u] = (idx == W_DIM - 1) ? (2.f * Mn2 - v) : v;
        }
        const float4 cf = make_coef(sy[gi - ilo], sy[gi + 1 - ilo], Mv[0], Mv[1]);
        sC[gi - kbase + 1] = cf;                        // slots 1004..1023
        if (t == 19) sC[1024] = cf;                     // pseudo interval 8191
    }
    __syncthreads();

    // ---- evaluate: static split; 2 LDS.128 + (MUL+SUB+3FMA)/pt, coalesced STG ----
    {
        float4* out4 = (float4*)outr;
        #pragma unroll
        for (int k = 0; k < TILE_I / NTHR; ++k) {
            const int cl = tid + k * NTHR;
            const int cg = kbase + cl;
            const float4 c0 = sC[cl];                   // interval cg-1 (A)
            const float4 c1 = sC[cl + 1];               // interval cg   (B)
            const float q0f = (float)(4 * cg);          // exact
            const float fi0 = (float)(cg - 1);          // exact

            // fq = rnd(q*step) matches reference xq bitwise; integer subtract
            // is Sterbenz-exact -> t bitwise == reference.
            #define FQ(m)  ((q0f + (float)(m)) * step)
            #define TA(m)  (FQ(m) - fi0)
            #define EVA(t) fmaf((t), fmaf((t), fmaf((t), c0.w, c0.z), c0.y), c0.x)
            #define EVB(t) fmaf((t), fmaf((t), fmaf((t), c1.w, c1.z), c1.y), c1.x)

            const int cg3 = 3 * cg;
            float4 r;
            if (cg3 > 16382) {                          // cg >= 5461
                if (cg == W_DIM - 1) {                  // cg == 8191: A A A A
                    r.x = EVA(TA(0)); r.y = EVA(TA(1));
                    r.z = EVA(TA(2)); r.w = EVA(TA(3));
                } else {                                // A A A B
                    r.x = EVA(TA(0)); r.y = EVA(TA(1));
                    r.z = EVA(TA(2)); r.w = EVB(TA(3) - 1.0f);
                }
            } else if (cg3 > 8191) {                    // cg in [2731,5460]: A A B B
                r.x = EVA(TA(0));        r.y = EVA(TA(1));
                r.z = EVB(TA(2) - 1.0f); r.w = EVB(TA(3) - 1.0f);
            } else if (cg3 > 0) {                       // cg in [1,2730]: A B B B
                r.x = EVA(TA(0));        r.y = EVB(TA(1) - 1.0f);
                r.z = EVB(TA(2) - 1.0f); r.w = EVB(TA(3) - 1.0f);
            } else {                                    // cg == 0: all interval 0
                r.x = EVB(FQ(0)); r.y = EVB(FQ(1));     // t = xq directly
                r.z = EVB(FQ(2)); r.w = EVB(FQ(3));
            }
            #undef FQ
            #undef TA
            #undef EVA
            #undef EVB
            out4[cl] = r;
        }
    }
}

extern "C" void kernel_launch(void* const* d_in, const int* in_sizes, int n_in,
                              void* d_out, int out_size) {
    const float* x = (const float*)d_in[0];
    float* out = (float*)d_out;

    const int B = in_sizes[0] / W_DIM;               // 512
    const int nout = out_size / B;                   // 32768
    const float step = (float)((double)(W_DIM - 1) / (double)(nout - 1));

    dim3 grid(W_DIM / TILE_I, B);                    // 8 x 512 = 4096 CTAs
    spline_kernel<<<grid, NTHR>>>(x, out, nout, step);
}

// round 13
// speedup vs baseline: 1.3209x; 1.3209x over previous
#include <cuda_runtime.h>

// Not-a-knot cubic spline upsample, 512 x 8192 fp32 -> 512 x 32768 fp32.
// [1,4,1] tridiagonal inverse = exponential Green's function (lam = sqrt(3)-2)
// composed with the 6*[1,-2,1] rhs into a 17-tap FIR on y -> M is LOCAL.
//
// step = 8191/32767: point m of chunk cg lies in interval cg-1 iff
// 8191*m < 3*cg (exact integer predicate) -> static warp-uniform A/B patterns,
// no floor/clamp/selects. Eval keeps R10's scalar-LDS + in-register coefficient
// build (the build arithmetic doubles as latency hiding for the LDS), but all
// per-point index math reduces to one ADD via u0 = fma(q0, step, -(cg-1)).

#define W_DIM  8192
#define NTHR   256
#define TILE_I 1024
#define KT     8
#define SYN    1056

#define LAM   (-0.26794919243112270647f)   // sqrt(3) - 2
#define ACOEF (0.28867513459481288225f)    // 1 / (2*sqrt(3))

__global__ __launch_bounds__(NTHR, 6)
void spline_kernel(const float* __restrict__ x, float* __restrict__ out,
                   int nout, float step) {
    __shared__ __align__(16) float syA[SYN + 8];   // 4-float zeroed front pad
    __shared__ __align__(16) float smA[SYN + 8];
    float* sy = syA + 4;
    float* sM = smA + 4;

    const int tid = threadIdx.x;
    const int n = W_DIM - 4;
    const int row = blockIdx.y;
    const int kbase = blockIdx.x * TILE_I;

    const float* xr = x + (size_t)row * W_DIM;
    float* outr = out + (size_t)row * nout + kbase * 4;

    const int ilo = (kbase >= 16) ? (kbase - 16) : 0;
    int ihi = kbase + TILE_I + 16; if (ihi > W_DIM) ihi = W_DIM;
    const int NY = ihi - ilo;

    // ---- load y slice (+halo), aligned float4; zero front pads ----
    {
        const float4* x4 = (const float4*)(xr + ilo);
        float4* sy4 = (float4*)sy;
        for (int v = tid; v < (NY >> 2); v += NTHR) sy4[v] = x4[v];
        if (tid < 4) { syA[tid] = 0.f; smA[tid] = 0.f; }
    }
    __syncthreads();

    // ---- interior M via 17-tap symmetric FIR on y -> sM ----
    {
        const float C0 = -4.3923048f;
        const float C[KT] = { 2.7846097f, -0.7461340f, 0.1999261f, -0.0535701f,
                              0.0143541f, -0.0038462f, 0.0010306f, -0.0002761f };
        const int FLO = (ilo == 0) ? 20 : 12;
        int ghi = kbase + TILE_I;
        if (ghi > W_DIM - 21) ghi = W_DIM - 21;
        const int nch = ((ghi - (ilo + FLO)) >> 2) + 1;
        for (int c = tid; c < nch; c += NTHR) {
            const int li0 = FLO + 4 * c;                // li0 % 4 == 0
            float win[20];                              // y[li0-8 .. li0+11]
            const float4* ws = (const float4*)(sy + li0 - 8);
            #pragma unroll
            for (int v = 0; v < 5; ++v) ((float4*)win)[v] = ws[v];
            #pragma unroll
            for (int m = 0; m < 4; ++m) {
                float acc = C0 * win[8 + m];
                #pragma unroll
                for (int k = 1; k <= KT; ++k)
                    acc = fmaf(C[k - 1], win[8 + m - k] + win[8 + m + k], acc);
                if (ilo + li0 + m <= ghi) sM[li0 + m] = acc;
            }
        }
    }

    // ---- left edge (row-start tile): exact M[0..19] via Green sums ----
    if (ilo == 0 && tid < 20) {
        const float M1 = sy[2] - 2.f * sy[1] + sy[0];
        float SL = 0.f, lp = LAM;
        #pragma unroll 4
        for (int j = 0; j < 24; ++j) {
            float b = 6.f * (sy[j + 3] - 2.f * sy[j + 2] + sy[j + 1]);
            if (j == 0) b -= M1;
            SL = fmaf(lp, b, SL);
            lp *= LAM;
        }
        float Mv;
        if (tid == 1) {
            Mv = M1;
        } else {
            const int jj = (tid == 0) ? 0 : tid - 2;
            float acc = 0.f, p = 1.f;
            #pragma unroll 4
            for (int d = 0; d <= 12; ++d) {
                const int j = jj - d;
                if (j >= 0) {
                    float b = 6.f * (sy[j + 3] - 2.f * sy[j + 2] + sy[j + 1]);
                    if (j == 0) b -= M1;
                    acc = fmaf(p, b, acc);
                }
                p *= LAM;
            }
            p = LAM;
            #pragma unroll 4
            for (int d = 1; d <= 12; ++d) {
                const int j = jj + d;                   // always < n
                float b = 6.f * (sy[j + 3] - 2.f * sy[j + 2] + sy[j + 1]);
                acc = fmaf(p, b, acc);
                p *= LAM;
            }
            float pw = LAM;                             // lam^{jj+1}
            for (int s = 0; s < jj; ++s) pw *= LAM;
            acc -= pw * SL;
            Mv = ACOEF * acc;
            if (tid == 0) Mv = 2.f * M1 - Mv;
        }
        sM[tid] = Mv;
    }

    // ---- right edge (row-end tile): exact M[W-20..W-1] ----
    if (kbase + TILE_I == W_DIM && tid >= 32 && tid < 52) {
        const int t = tid - 32;
        const int gi = W_DIM - 20 + t;
        const int lW = W_DIM - ilo;
        const float Mn2 = sy[lW - 1] - 2.f * sy[lW - 2] + sy[lW - 3];
        float SR = 0.f, lp = LAM;
        #pragma unroll 4
        for (int m = 0; m < 24; ++m) {
            const int j = n - 1 - m;
            float b = 6.f * (sy[j + 3 - ilo] - 2.f * sy[j + 2 - ilo] + sy[j + 1 - ilo]);
            if (j == n - 1) b -= Mn2;
            SR = fmaf(lp, b, SR);
            lp *= LAM;
        }
        float Mv;
        if (t == 18) {
            Mv = Mn2;                                   // gi == W-2
        } else {
            const int jj = (t == 19) ? (n - 1) : (gi - 2);
            float acc = 0.f, p = 1.f;
            #pragma unroll 4
            for (int d = 0; d <= 12; ++d) {
                const int j = jj - d;                   // always >= 0
                float b = 6.f * (sy[j + 3 - ilo] - 2.f * sy[j + 2 - ilo] + sy[j + 1 - ilo]);
                if (j == n - 1) b -= Mn2;
                acc = fmaf(p, b, acc);
                p *= LAM;
            }
            p = LAM;
            #pragma unroll 4
            for (int d = 1; d <= 12; ++d) {
                const int j = jj + d;
                if (j < n) {
                    float b = 6.f * (sy[j + 3 - ilo] - 2.f * sy[j + 2 - ilo] + sy[j + 1 - ilo]);
                    acc = fmaf(p, b, acc);
                }
                p *= LAM;
            }
            float pw = LAM;                             // lam^{n-jj}
            for (int s = 0; s < n - 1 - jj; ++s) pw *= LAM;
            acc -= pw * SR;
            Mv = ACOEF * acc;
            if (t == 19) Mv = 2.f * Mn2 - Mv;
        }
        sM[gi - ilo] = Mv;
    }
    __syncthreads();

    // ---- evaluate: static split; per chunk 1 FMA + 1 SUB index math,
    //      per point 1 ADD + 3 FMA ----
    {
        float4* out4 = (float4*)outr;
        const int loff = kbase - 1 - ilo;               // 15 interior, -1 first tile
        const float s1 = step;
        const float s2 = step + step;                   // exact
        const float s3 = 3.0f * step;                   // 1 rounding, ~1e-7 t jitter
        #pragma unroll
        for (int k = 0; k < TILE_I / NTHR; ++k) {
            const int cl = tid + k * NTHR;
            const int cg = kbase + cl;
            const int iL = cl + loff;
            const float q0f = (float)(4 * cg);          // exact
            const float fi0 = (float)(cg - 1);          // exact
            const float u0 = fmaf(q0f, step, -fi0);     // t of pt 0 on A, 0.5ulp
            const float ub0 = u0 - 1.0f;                // t of pt 0 on B, exact

            const float y0 = sy[iL], y1 = sy[iL + 1], y2 = sy[iL + 2];
            const float m0 = sM[iL], m1 = sM[iL + 1], m2 = sM[iL + 2];
            const float Ax = y0;
            const float Ay = fmaf(fmaf(2.f, m0, m1), -(1.f / 6.f), y1 - y0);
            const float Az = 0.5f * m0;
            const float Aw = (m1 - m0) * (1.f / 6.f);
            const float Bx = y1;
            const float By = fmaf(fmaf(2.f, m1, m2), -(1.f / 6.f), y2 - y1);
            const float Bz = 0.5f * m1;
            const float Bw = (m2 - m1) * (1.f / 6.f);

            #define EVA(t) fmaf((t), fmaf((t), fmaf((t), Aw, Az), Ay), Ax)
            #define EVB(t) fmaf((t), fmaf((t), fmaf((t), Bw, Bz), By), Bx)

            const int cg3 = 3 * cg;
            float4 r;
            if (cg3 > 16382) {                          // cg >= 5461
                if (cg == W_DIM - 1) {                  // cg == 8191: A A A A
                    r.x = EVA(u0);      r.y = EVA(u0 + s1);
                    r.z = EVA(u0 + s2); r.w = EVA(u0 + s3);
                } else {                                // A A A B
                    r.x = EVA(u0);      r.y = EVA(u0 + s1);
                    r.z = EVA(u0 + s2); r.w = EVB(ub0 + s3);
                }
            } else if (cg3 > 8191) {                    // cg in [2731,5460]: A A B B
                r.x = EVA(u0);       r.y = EVA(u0 + s1);
                r.z = EVB(ub0 + s2); r.w = EVB(ub0 + s3);
            } else if (cg3 > 0) {                       // cg in [1,2730]: A B B B
                r.x = EVA(u0);       r.y = EVB(ub0 + s1);
                r.z = EVB(ub0 + s2); r.w = EVB(ub0 + s3);
            } else {                                    // cg == 0 (fi0 = -1): B B B B
                r.x = EVB(ub0);      r.y = EVB(ub0 + s1);
                r.z = EVB(ub0 + s2); r.w = EVB(ub0 + s3);
            }
            #undef EVA
            #undef EVB
            out4[cl] = r;
        }
    }
}

extern "C" void kernel_launch(void* const* d_in, const int* in_sizes, int n_in,
                              void* d_out, int out_size) {
    const float* x = (const float*)d_in[0];
    float* out = (float*)d_out;

    const int B = in_sizes[0] / W_DIM;               // 512
    const int nout = out_size / B;                   // 32768
    const float step = (float)((double)(W_DIM - 1) / (double)(nout - 1));

    dim3 grid(W_DIM / TILE_I, B);                    // 8 x 512 = 4096 CTAs
    spline_kernel<<<grid, NTHR>>>(x, out, nout, step);
}

// round 14
// speedup vs baseline: 1.3243x; 1.0026x over previous
#include <cuda_runtime.h>

// Not-a-knot cubic spline upsample, 512 x 8192 fp32 -> 512 x 32768 fp32.
// [1,4,1] tridiagonal inverse = exponential Green's function (lam = sqrt(3)-2)
// composed with the 6*[1,-2,1] rhs into a 17-tap FIR on y -> M is LOCAL.
//
// step = 8191/32767: point m of chunk cg lies in interval cg-1 iff
// 8191*m < 3*cg (exact integer predicate) -> static warp-uniform A/B patterns.
// Eval uses PACKED f32x2 math (fma.rn.f32x2): the two interval coefficient
// sets (A|B) build in 6 packed ops from knot pairs, and points (0,2)/(1,3)
// evaluate as packed Horner pairs. Each lane rounds exactly like scalar fmaf
// -> bit-identical to the scalar version.

#define W_DIM  8192
#define NTHR   256
#define TILE_I 1024
#define KT     8
#define SYN    1056

#define LAM   (-0.26794919243112270647f)   // sqrt(3) - 2
#define ACOEF (0.28867513459481288225f)    // 1 / (2*sqrt(3))

typedef unsigned long long u64p;

__device__ __forceinline__ u64p pk(float lo, float hi) {
    u64p r;
    asm("mov.b64 %0, {%1, %2};" : "=l"(r) : "f"(lo), "f"(hi));
    return r;
}
__device__ __forceinline__ void upk(u64p v, float& lo, float& hi) {
    asm("mov.b64 {%0, %1}, %2;" : "=f"(lo), "=f"(hi) : "l"(v));
}
__device__ __forceinline__ u64p fma2(u64p a, u64p b, u64p c) {
    u64p r;
    asm("fma.rn.f32x2 %0, %1, %2, %3;" : "=l"(r) : "l"(a), "l"(b), "l"(c));
    return r;
}
__device__ __forceinline__ u64p mul2(u64p a, u64p b) {
    u64p r;
    asm("mul.rn.f32x2 %0, %1, %2;" : "=l"(r) : "l"(a), "l"(b));
    return r;
}
__device__ __forceinline__ u64p dup_lo(u64p v) {
    u64p r;
    asm("{ .reg .b32 lo, hi;\n\t"
        "mov.b64 {lo, hi}, %1;\n\t"
        "mov.b64 %0, {lo, lo}; }" : "=l"(r) : "l"(v));
    return r;
}
__device__ __forceinline__ u64p dup_hi(u64p v) {
    u64p r;
    asm("{ .reg .b32 lo, hi;\n\t"
        "mov.b64 {lo, hi}, %1;\n\t"
        "mov.b64 %0, {hi, hi}; }" : "=l"(r) : "l"(v));
    return r;
}
__device__ __forceinline__ u64p ev2(u64p t, u64p cw, u64p cz, u64p cy, u64p cx) {
    return fma2(t, fma2(t, fma2(t, cw, cz), cy), cx);
}

__global__ __launch_bounds__(NTHR, 6)
void spline_kernel(const float* __restrict__ x, float* __restrict__ out,
                   int nout, float step) {
    __shared__ __align__(16) float syA[SYN + 8];   // 4-float zeroed front pad
    __shared__ __align__(16) float smA[SYN + 8];
    float* sy = syA + 4;
    float* sM = smA + 4;

    const int tid = threadIdx.x;
    const int n = W_DIM - 4;
    const int row = blockIdx.y;
    const int kbase = blockIdx.x * TILE_I;

    const float* xr = x + (size_t)row * W_DIM;
    float* outr = out + (size_t)row * nout + kbase * 4;

    const int ilo = (kbase >= 16) ? (kbase - 16) : 0;
    int ihi = kbase + TILE_I + 16; if (ihi > W_DIM) ihi = W_DIM;
    const int NY = ihi - ilo;

    // ---- load y slice (+halo), aligned float4; zero front pads ----
    {
        const float4* x4 = (const float4*)(xr + ilo);
        float4* sy4 = (float4*)sy;
        for (int v = tid; v < (NY >> 2); v += NTHR) sy4[v] = x4[v];
        if (tid < 4) { syA[tid] = 0.f; smA[tid] = 0.f; }
    }
    __syncthreads();

    // ---- interior M via 17-tap symmetric FIR on y -> sM ----
    {
        const float C0 = -4.3923048f;
        const float C[KT] = { 2.7846097f, -0.7461340f, 0.1999261f, -0.0535701f,
                              0.0143541f, -0.0038462f, 0.0010306f, -0.0002761f };
        const int FLO = (ilo == 0) ? 20 : 12;
        int ghi = kbase + TILE_I;
        if (ghi > W_DIM - 21) ghi = W_DIM - 21;
        const int nch = ((ghi - (ilo + FLO)) >> 2) + 1;
        for (int c = tid; c < nch; c += NTHR) {
            const int li0 = FLO + 4 * c;                // li0 % 4 == 0
            float win[20];                              // y[li0-8 .. li0+11]
            const float4* ws = (const float4*)(sy + li0 - 8);
            #pragma unroll
            for (int v = 0; v < 5; ++v) ((float4*)win)[v] = ws[v];
            #pragma unroll
            for (int m = 0; m < 4; ++m) {
                float acc = C0 * win[8 + m];
                #pragma unroll
                for (int k = 1; k <= KT; ++k)
                    acc = fmaf(C[k - 1], win[8 + m - k] + win[8 + m + k], acc);
                if (ilo + li0 + m <= ghi) sM[li0 + m] = acc;
            }
        }
    }

    // ---- left edge (row-start tile): exact M[0..19] via Green sums ----
    if (ilo == 0 && tid < 20) {
        const float M1 = sy[2] - 2.f * sy[1] + sy[0];
        float SL = 0.f, lp = LAM;
        #pragma unroll 4
        for (int j = 0; j < 24; ++j) {
            float b = 6.f * (sy[j + 3] - 2.f * sy[j + 2] + sy[j + 1]);
            if (j == 0) b -= M1;
            SL = fmaf(lp, b, SL);
            lp *= LAM;
        }
        float Mv;
        if (tid == 1) {
            Mv = M1;
        } else {
            const int jj = (tid == 0) ? 0 : tid - 2;
            float acc = 0.f, p = 1.f;
            #pragma unroll 4
            for (int d = 0; d <= 12; ++d) {
                const int j = jj - d;
                if (j >= 0) {
                    float b = 6.f * (sy[j + 3] - 2.f * sy[j + 2] + sy[j + 1]);
                    if (j == 0) b -= M1;
                    acc = fmaf(p, b, acc);
                }
                p *= LAM;
            }
            p = LAM;
            #pragma unroll 4
            for (int d = 1; d <= 12; ++d) {
                const int j = jj + d;                   // always < n
                float b = 6.f * (sy[j + 3] - 2.f * sy[j + 2] + sy[j + 1]);
                acc = fmaf(p, b, acc);
                p *= LAM;
            }
            float pw = LAM;                             // lam^{jj+1}
            for (int s = 0; s < jj; ++s) pw *= LAM;
            acc -= pw * SL;
            Mv = ACOEF * acc;
            if (tid == 0) Mv = 2.f * M1 - Mv;
        }
        sM[tid] = Mv;
    }

    // ---- right edge (row-end tile): exact M[W-20..W-1] ----
    if (kbase + TILE_I == W_DIM && tid >= 32 && tid < 52) {
        const int t = tid - 32;
        const int gi = W_DIM - 20 + t;
        const int lW = W_DIM - ilo;
        const float Mn2 = sy[lW - 1] - 2.f * sy[lW - 2] + sy[lW - 3];
        float SR = 0.f, lp = LAM;
        #pragma unroll 4
        for (int m = 0; m < 24; ++m) {
            const int j = n - 1 - m;
            float b = 6.f * (sy[j + 3 - ilo] - 2.f * sy[j + 2 - ilo] + sy[j + 1 - ilo]);
            if (j == n - 1) b -= Mn2;
            SR = fmaf(lp, b, SR);
            lp *= LAM;
        }
        float Mv;
        if (t == 18) {
            Mv = Mn2;                                   // gi == W-2
        } else {
            const int jj = (t == 19) ? (n - 1) : (gi - 2);
            float acc = 0.f, p = 1.f;
            #pragma unroll 4
            for (int d = 0; d <= 12; ++d) {
                const int j = jj - d;                   // always >= 0
                float b = 6.f * (sy[j + 3 - ilo] - 2.f * sy[j + 2 - ilo] + sy[j + 1 - ilo]);
                if (j == n - 1) b -= Mn2;
                acc = fmaf(p, b, acc);
                p *= LAM;
            }
            p = LAM;
            #pragma unroll 4
            for (int d = 1; d <= 12; ++d) {
                const int j = jj + d;
                if (j < n) {
                    float b = 6.f * (sy[j + 3 - ilo] - 2.f * sy[j + 2 - ilo] + sy[j + 1 - ilo]);
                    acc = fmaf(p, b, acc);
                }
                p *= LAM;
            }
            float pw = LAM;                             // lam^{n-jj}
            for (int s = 0; s < n - 1 - jj; ++s) pw *= LAM;
            acc -= pw * SR;
            Mv = ACOEF * acc;
            if (t == 19) Mv = 2.f * Mn2 - Mv;
        }
        sM[gi - ilo] = Mv;
    }
    __syncthreads();

    // ---- evaluate: packed f32x2 build + packed Horner over point pairs ----
    {
        float4* out4 = (float4*)outr;
        const int loff = kbase - 1 - ilo;
        const float s1 = step;
        const float s2 = step + step;                   // exact
        const float s3 = 3.0f * step;
        const u64p cTWO  = pk(2.0f, 2.0f);
        const u64p cNEG1 = pk(-1.0f, -1.0f);
        const u64p cNS6  = pk(-(1.f / 6.f), -(1.f / 6.f));
        const u64p cHALF = pk(0.5f, 0.5f);
        const u64p cS6   = pk(1.f / 6.f, 1.f / 6.f);

        #pragma unroll
        for (int k = 0; k < TILE_I / NTHR; ++k) {
            const int cl = tid + k * NTHR;
            const int cg = kbase + cl;
            const int iL = cl + loff;
            const float q0f = (float)(4 * cg);          // exact
            const float fi0 = (float)(cg - 1);          // exact
            const float u0 = fmaf(q0f, step, -fi0);     // t of pt0 on A
            const float ub0 = u0 - 1.0f;                // t of pt0 on B, exact

            const float y0 = sy[iL], y1 = sy[iL + 1], y2 = sy[iL + 2];
            const float m0 = sM[iL], m1 = sM[iL + 1], m2 = sM[iL + 2];

            // packed coefficient pair: lane0 = interval cg-1 (A), lane1 = cg (B)
            const u64p y01 = pk(y0, y1);
            const u64p y12 = pk(y1, y2);
            const u64p m01 = pk(m0, m1);
            const u64p m12 = pk(m1, m2);
            const u64p dy2 = fma2(y01, cNEG1, y12);     // (y1-y0 | y2-y1)
            const u64p cy2 = fma2(fma2(cTWO, m01, m12), cNS6, dy2);
            const u64p cz2 = mul2(m01, cHALF);
            const u64p cw2 = mul2(fma2(m01, cNEG1, m12), cS6);
            const u64p cx2 = y01;

            const int cg3 = 3 * cg;
            u64p r02, r13;
            if (cg3 > 16382) {                          // cg >= 5461
                const u64p xx = dup_lo(cx2), yy = dup_lo(cy2);
                const u64p zz = dup_lo(cz2), ww = dup_lo(cw2);
                r02 = ev2(pk(u0, u0 + s2), ww, zz, yy, xx);        // (A,A)
                if (cg == W_DIM - 1)                               // AAAA
                    r13 = ev2(pk(u0 + s1, u0 + s3), ww, zz, yy, xx);
                else                                               // AAAB
                    r13 = ev2(pk(u0 + s1, ub0 + s3), cw2, cz2, cy2, cx2);
            } else if (cg3 > 8191) {                    // AABB: both pairs (A,B)
                r02 = ev2(pk(u0, ub0 + s2), cw2, cz2, cy2, cx2);
                r13 = ev2(pk(u0 + s1, ub0 + s3), cw2, cz2, cy2, cx2);
            } else if (cg3 > 0) {                       // ABBB
                const u64p xx = dup_hi(cx2), yy = dup_hi(cy2);
                const u64p zz = dup_hi(cz2), ww = dup_hi(cw2);
                r02 = ev2(pk(u0, ub0 + s2), cw2, cz2, cy2, cx2);   // (A,B)
                r13 = ev2(pk(ub0 + s1, ub0 + s3), ww, zz, yy, xx); // (B,B)
            } else {                                    // cg == 0: BBBB
                const u64p xx = dup_hi(cx2), yy = dup_hi(cy2);
                const u64p zz = dup_hi(cz2), ww = dup_hi(cw2);
                r02 = ev2(pk(ub0, ub0 + s2), ww, zz, yy, xx);
                r13 = ev2(pk(ub0 + s1, ub0 + s3), ww, zz, yy, xx);
            }

            float4 r;
            upk(r02, r.x, r.z);                         // points 0, 2
            upk(r13, r.y, r.w);                         // points 1, 3
            out4[cl] = r;
        }
    }
}

extern "C" void kernel_launch(void* const* d_in, const int* in_sizes, int n_in,
                              void* d_out, int out_size) {
    const float* x = (const float*)d_in[0];
    float* out = (float*)d_out;

    const int B = in_sizes[0] / W_DIM;               // 512
    const int nout = out_size / B;                   // 32768
    const float step = (float)((double)(W_DIM - 1) / (double)(nout - 1));

    dim3 grid(W_DIM / TILE_I, B);                    // 8 x 512 = 4096 CTAs
    spline_kernel<<<grid, NTHR>>>(x, out, nout, step);
}